// round 1
// baseline (speedup 1.0000x reference)
#include <cuda_runtime.h>
#include <cuda_fp16.h>
#include <math.h>

#define BB  8
#define HH  640
#define WW  368
#define HW  (HH*WW)      // 235520
#define TOT (BB*HH*WW)   // 1884160

// ---------------- scratch (static device memory is allowed) ----------------
__device__ float2 g_bufA[TOT];   // 15 MB
__device__ float2 g_bufB[TOT];   // 15 MB

// twiddle / small-DFT tables (e^{+2*pi*i*t/N} -> inverse transform)
__device__ float2 g_w23[23];
__device__ float2 g_w16[16];
__device__ float2 g_tw368[368];
__device__ float2 g_w20[20];
__device__ float2 g_w32[32];
__device__ float2 g_tw640[640];
__device__ float2 g_w8[8];

__device__ __forceinline__ float2 cmulf(float2 a, float2 b) {
    return make_float2(fmaf(a.x, b.x, -a.y * b.y), fmaf(a.x, b.y, a.y * b.x));
}
__device__ __forceinline__ void cfma(float2& acc, float2 a, float2 b) {
    acc.x = fmaf(a.x, b.x, fmaf(-a.y, b.y, acc.x));
    acc.y = fmaf(a.x, b.y, fmaf( a.y, b.x, acc.y));
}

// ---------------- table init (runs every launch; deterministic) ------------
__device__ __forceinline__ void fill_tw(float2* arr, int N, int i) {
    double a = 6.283185307179586476925286766559 * (double)i / (double)N;
    double s, c;
    sincos(a, &s, &c);
    arr[i] = make_float2((float)c, (float)s);
}

__global__ void k_init() {
    int t = blockIdx.x * blockDim.x + threadIdx.x;
    if      (t < 23)          fill_tw(g_w23,   23,  t);
    else if (t < 23+16)       fill_tw(g_w16,   16,  t-23);
    else if (t < 39+368)      fill_tw(g_tw368, 368, t-39);
    else if (t < 407+20)      fill_tw(g_w20,   20,  t-407);
    else if (t < 427+32)      fill_tw(g_w32,   32,  t-427);
    else if (t < 459+640)     fill_tw(g_tw640, 640, t-459);
    else if (t < 1099+8)      fill_tw(g_w8,    8,   t-1099);
}

// ---------------- fused conv3x3(2->32)+leaky + conv1x1(32->2)+leaky --------
// writes complex field * (-1)^(b+h+w) * 1/sqrt(B*H*W) into g_bufA
__global__ void k_conv1(const float* __restrict__ ks, const float* __restrict__ wk,
                        const float* __restrict__ bk, const float* __restrict__ w1,
                        const float* __restrict__ b1) {
    __shared__ float swk[576];
    __shared__ float sbk[32];
    __shared__ float sw1[64];
    __shared__ float sb1[2];
    for (int i = threadIdx.x; i < 576; i += blockDim.x) swk[i] = wk[i];
    if (threadIdx.x < 32) sbk[threadIdx.x] = bk[threadIdx.x];
    if (threadIdx.x < 64) sw1[threadIdx.x] = w1[threadIdx.x];
    if (threadIdx.x < 2)  sb1[threadIdx.x] = b1[threadIdx.x];
    __syncthreads();

    int pix = blockIdx.x * blockDim.x + threadIdx.x;
    if (pix >= TOT) return;
    int w = pix % WW;
    int h = (pix / WW) % HH;
    int b = pix / HW;

    float x[2][9];
#pragma unroll
    for (int c = 0; c < 2; c++) {
        const float* base = ks + (size_t)(b * 2 + c) * HW;
#pragma unroll
        for (int ky = 0; ky < 3; ky++) {
            int hh = h + ky - 1;
#pragma unroll
            for (int kx = 0; kx < 3; kx++) {
                int ww = w + kx - 1;
                float v = 0.0f;
                if (hh >= 0 && hh < HH && ww >= 0 && ww < WW)
                    v = __ldg(base + hh * WW + ww);
                x[c][ky * 3 + kx] = v;
            }
        }
    }

    float o0 = 0.0f, o1 = 0.0f;
#pragma unroll 4
    for (int o = 0; o < 32; o++) {
        float acc = sbk[o];
        const float* wo = swk + o * 18;
#pragma unroll
        for (int c = 0; c < 2; c++)
#pragma unroll
            for (int t = 0; t < 9; t++)
                acc = fmaf(wo[c * 9 + t], x[c][t], acc);
        acc = acc >= 0.0f ? acc : 0.01f * acc;     // leaky
        o0 = fmaf(sw1[o],      acc, o0);
        o1 = fmaf(sw1[32 + o], acc, o1);
    }
    o0 += sb1[0]; o0 = o0 >= 0.0f ? o0 : 0.01f * o0;
    o1 += sb1[1]; o1 = o1 >= 0.0f ? o1 : 0.01f * o1;

    // centered-ifft input sign flip + ortho normalization (folded once here)
    float norm = rsqrtf((float)TOT);
    float s = ((b + h + w) & 1) ? -norm : norm;
    g_bufA[pix] = make_float2(o0 * s, o1 * s);
}

// ---------------- W axis: 368 = 16 (N1) x 23 (N2) --------------------------
// stage 1: T[n1*23+k2] = tw368[n1*k2] * sum_{n2<23} x[n1+16*n2] * w23[(n2*k2)%23]
__global__ void k_w1() {
    int t = blockIdx.x * blockDim.x + threadIdx.x;
    if (t >= TOT) return;
    int j = t % WW;
    int row = t / WW;
    int n1 = j / 23, k2 = j % 23;
    const float2* in = g_bufA + (size_t)row * WW;
    float2 acc = make_float2(0.0f, 0.0f);
    int idx = 0;
#pragma unroll
    for (int n2 = 0; n2 < 23; n2++) {
        cfma(acc, in[n1 + 16 * n2], g_w23[idx]);
        idx += k2; if (idx >= 23) idx -= 23;
    }
    g_bufB[(size_t)row * WW + n1 * 23 + k2] = cmulf(acc, g_tw368[n1 * k2]);
}

// stage 2: X[23*k1+k2] = sum_{n1<16} T[n1*23+k2] * w16[(n1*k1)&15]
__global__ void k_w2() {
    int t = blockIdx.x * blockDim.x + threadIdx.x;
    if (t >= TOT) return;
    int j = t % WW;
    int row = t / WW;
    int k1 = j / 23, k2 = j % 23;
    const float2* in = g_bufB + (size_t)row * WW;
    float2 acc = make_float2(0.0f, 0.0f);
#pragma unroll
    for (int n1 = 0; n1 < 16; n1++)
        cfma(acc, in[n1 * 23 + k2], g_w16[(n1 * k1) & 15]);
    g_bufA[(size_t)row * WW + j] = acc;
}

// ---------------- H axis: 640 = 32 (N1) x 20 (N2) --------------------------
// stage 1: thread = (b, n1, w), computes all 20 k2 outputs
__global__ void k_h1() {
    int t = blockIdx.x * blockDim.x + threadIdx.x;
    if (t >= BB * 32 * WW) return;
    int w  = t % WW;
    int n1 = (t / WW) % 32;
    int b  = t / (WW * 32);
    const float2* in = g_bufA + (size_t)b * HW + w;
    float2 acc[20];
#pragma unroll
    for (int k2 = 0; k2 < 20; k2++) acc[k2] = make_float2(0.0f, 0.0f);
#pragma unroll
    for (int n2 = 0; n2 < 20; n2++) {
        float2 v = in[(size_t)(n1 + 32 * n2) * WW];
        int idx = 0;
#pragma unroll
        for (int k2 = 0; k2 < 20; k2++) {
            cfma(acc[k2], v, g_w20[idx]);
            idx += n2; if (idx >= 20) idx -= 20;
        }
    }
    float2* out = g_bufB + (size_t)b * HW + w;
#pragma unroll
    for (int k2 = 0; k2 < 20; k2++)
        out[(size_t)(n1 * 20 + k2) * WW] = cmulf(acc[k2], g_tw640[n1 * k2]);
}

// stage 2: thread = (b, k2, w, k1-block of 8), X[20*k1+k2] = sum_{n1<32} T[n1*20+k2]*w32[(n1*k1)&31]
__global__ void k_h2() {
    int t = blockIdx.x * blockDim.x + threadIdx.x;
    if (t >= BB * 20 * WW * 4) return;
    int w   = t % WW;
    int r   = t / WW;
    int k2  = r % 20;  r /= 20;
    int k1b = r % 4;
    int b   = r / 4;
    const float2* in = g_bufB + (size_t)b * HW + w;
    float2 acc[8];
#pragma unroll
    for (int i = 0; i < 8; i++) acc[i] = make_float2(0.0f, 0.0f);
#pragma unroll
    for (int n1 = 0; n1 < 32; n1++) {
        float2 v = in[(size_t)(n1 * 20 + k2) * WW];
#pragma unroll
        for (int i = 0; i < 8; i++) {
            int k1 = k1b * 8 + i;
            cfma(acc[i], v, g_w32[(n1 * k1) & 31]);
        }
    }
    float2* out = g_bufA + (size_t)b * HW + w;
#pragma unroll
    for (int i = 0; i < 8; i++)
        out[(size_t)(20 * (k1b * 8 + i) + k2) * WW] = acc[i];
}

// ---------------- batch radix-8 DFT + abs + fp16 conv1x1(2->1)+leaky -------
// reads g_bufA, writes f32 tmp into g_bufB (reinterpreted as float*)
__global__ void k_babs(const float* __restrict__ img, const float* __restrict__ w2,
                       const float* __restrict__ b2) {
    int p = blockIdx.x * blockDim.x + threadIdx.x;
    if (p >= HW) return;

    float2 xin[8];
#pragma unroll
    for (int bb = 0; bb < 8; bb++) xin[bb] = g_bufA[(size_t)bb * HW + p];

    // replicate torch .half() rounding of weights
    float cw0 = __half2float(__float2half(__ldg(w2)));
    float cw1 = __half2float(__float2half(__ldg(w2 + 1)));
    __half b2h = __float2half(__ldg(b2));
    const __half slope = __float2half(0.01f);

    float* tmp = (float*)g_bufB;
#pragma unroll
    for (int k = 0; k < 8; k++) {
        float2 acc = make_float2(0.0f, 0.0f);
#pragma unroll
        for (int bb = 0; bb < 8; bb++)
            cfma(acc, xin[bb], g_w8[(bb * k) & 7]);
        float im = sqrtf(fmaf(acc.x, acc.x, acc.y * acc.y));

        // fp16 path: round inputs to half, f32 dot, round to half, +bias, half leaky
        float imh  = __half2float(__float2half(im));
        float imgv = __half2float(__float2half(__ldg(img + (size_t)k * HW + p)));
        float y = fmaf(cw1, imgv, cw0 * imh);
        __half yh = __float2half(y);
        yh = __hadd(yh, b2h);
        float yf = __half2float(yh);
        float z = (yf >= 0.0f) ? yf : __half2float(__hmul(yh, slope));
        tmp[(size_t)k * HW + p] = z;
    }
}

// ---------------- final conv3x3(1->1) pad1 + leaky -> d_out ----------------
__global__ void k_final(float* __restrict__ out, const float* __restrict__ wi,
                        const float* __restrict__ bi) {
    int pix = blockIdx.x * blockDim.x + threadIdx.x;
    if (pix >= TOT) return;
    int w = pix % WW;
    int h = (pix / WW) % HH;
    int b = pix / HW;
    const float* tmp = (const float*)g_bufB + (size_t)b * HW;
    float acc = __ldg(bi);
#pragma unroll
    for (int ky = 0; ky < 3; ky++) {
        int hh = h + ky - 1;
        if (hh < 0 || hh >= HH) continue;
#pragma unroll
        for (int kx = 0; kx < 3; kx++) {
            int ww = w + kx - 1;
            if (ww < 0 || ww >= WW) continue;
            acc = fmaf(__ldg(wi + ky * 3 + kx), tmp[hh * WW + ww], acc);
        }
    }
    out[pix] = acc >= 0.0f ? acc : 0.01f * acc;
}

// ---------------------------------------------------------------------------
extern "C" void kernel_launch(void* const* d_in, const int* in_sizes, int n_in,
                              void* d_out, int out_size) {
    const float* img = (const float*)d_in[0];
    const float* ks  = (const float*)d_in[1];
    const float* wk  = (const float*)d_in[2];
    const float* bk  = (const float*)d_in[3];
    const float* w1  = (const float*)d_in[4];
    const float* b1  = (const float*)d_in[5];
    const float* w2  = (const float*)d_in[6];
    const float* b2  = (const float*)d_in[7];
    const float* wi  = (const float*)d_in[8];
    const float* bi  = (const float*)d_in[9];

    k_init <<<5, 256>>>();
    k_conv1<<<(TOT + 255) / 256, 256>>>(ks, wk, bk, w1, b1);
    k_w1   <<<(TOT + 255) / 256, 256>>>();
    k_w2   <<<(TOT + 255) / 256, 256>>>();
    k_h1   <<<(BB * 32 * WW + 255) / 256, 256>>>();
    k_h2   <<<(BB * 20 * WW * 4 + 255) / 256, 256>>>();
    k_babs <<<(HW + 255) / 256, 256>>>(img, w2, b2);
    k_final<<<(TOT + 255) / 256, 256>>>((float*)d_out, wi, bi);
}

// round 4
// speedup vs baseline: 1.0783x; 1.0783x over previous
#include <cuda_runtime.h>
#include <cuda_fp16.h>
#include <math.h>

#define BB  8
#define HH  640
#define WW  368
#define HW  (HH*WW)      // 235520
#define TOT (BB*HH*WW)   // 1884160

typedef unsigned long long u64;

// ---------------- scratch ----------------
__device__ float2 g_bufA[TOT];   // 15 MB
__device__ float2 g_bufB[TOT];   // 15 MB

// twiddle tables (e^{+2*pi*i*t/N} -> inverse transform)
__device__ float2 g_w23[23];
__device__ float2 g_w16[16];
__device__ float2 g_tw368[368];
__device__ float2 g_tw640[640];
// packed tables: .x = pk(c,s), .y = pk(s,c)   (value-reuse complex fma form)
__device__ ulonglong2 g_w20q[20];
__device__ ulonglong2 g_w8q[8];
// packed table: .x = pk(c,c), .y = pk(-s,s)   (weight-reuse complex fma form)
__device__ ulonglong2 g_w32q[32];

// ---------------- f32x2 helpers ----------------
__device__ __forceinline__ u64 pk(float lo, float hi) {
    u64 r; asm("mov.b64 %0, {%1, %2};" : "=l"(r) : "f"(lo), "f"(hi)); return r;
}
__device__ __forceinline__ void upk(u64 v, float& lo, float& hi) {
    asm("mov.b64 {%0, %1}, %2;" : "=f"(lo), "=f"(hi) : "l"(v));
}
__device__ __forceinline__ u64 ffma2(u64 a, u64 b, u64 c) {
    u64 d; asm("fma.rn.f32x2 %0, %1, %2, %3;" : "=l"(d) : "l"(a), "l"(b), "l"(c)); return d;
}

__device__ __forceinline__ float2 cmulf(float2 a, float2 b) {
    return make_float2(fmaf(a.x, b.x, -a.y * b.y), fmaf(a.x, b.y, a.y * b.x));
}
__device__ __forceinline__ void cfma(float2& acc, float2 a, float2 b) {
    acc.x = fmaf(a.x, b.x, fmaf(-a.y, b.y, acc.x));
    acc.y = fmaf(a.x, b.y, fmaf( a.y, b.x, acc.y));
}
__device__ __forceinline__ float leaky(float a) {
    return fmaf(0.01f, fminf(a, 0.0f), fmaxf(a, 0.0f));
}

// ---------------- table init ----------------
__device__ __forceinline__ void csN(int N, int i, float& c, float& s) {
    double a = 6.283185307179586476925286766559 * (double)i / (double)N;
    double ds, dc; sincos(a, &ds, &dc);
    c = (float)dc; s = (float)ds;
}
__device__ __forceinline__ u64 pkh(float lo, float hi) {
    return ((u64)__float_as_uint(hi) << 32) | (u64)__float_as_uint(lo);
}

__global__ void k_init() {
    int t = blockIdx.x * blockDim.x + threadIdx.x;
    float c, s;
    if (t < 23)               { csN(23,  t,        c, s); g_w23[t]        = make_float2(c, s); }
    else if (t < 39)          { csN(16,  t-23,     c, s); g_w16[t-23]     = make_float2(c, s); }
    else if (t < 39+368)      { csN(368, t-39,     c, s); g_tw368[t-39]   = make_float2(c, s); }
    else if (t < 407+640)     { csN(640, t-407,    c, s); g_tw640[t-407]  = make_float2(c, s); }
    else if (t < 1047+20)     { csN(20,  t-1047,   c, s); g_w20q[t-1047]  = make_ulonglong2(pkh(c, s), pkh(s, c)); }
    else if (t < 1067+32)     { csN(32,  t-1067,   c, s); g_w32q[t-1067]  = make_ulonglong2(pkh(c, c), pkh(-s, s)); }
    else if (t < 1099+8)      { csN(8,   t-1099,   c, s); g_w8q[t-1099]   = make_ulonglong2(pkh(c, s), pkh(s, c)); }
}

// =====================================================================
// Kernel A: conv3x3(2->32)+leaky + conv1x1(32->2)+leaky  +  W-axis FFT
//           (368 = 16 x 23), fully fused per block of RA rows.
// Writes result (with centered-ifft sign + ortho norm) to g_bufB.
// =====================================================================
#define RA 8
__global__ __launch_bounds__(384) void k_convW(const float* __restrict__ ks,
        const float* __restrict__ wk, const float* __restrict__ bk,
        const float* __restrict__ w1, const float* __restrict__ b1) {
    __shared__ float2 srow[RA][WW];   // 23552 B
    __shared__ u64    spw[288];       // packed conv3x3 weights (16 ch-pairs x 18 taps)
    __shared__ u64    spb[16];
    __shared__ u64    sr1[32];        // (w1[0][o], w1[1][o])
    __shared__ float2 sw23[23];
    __shared__ float2 sw16[16];
    __shared__ float2 stw[WW];
    __shared__ float  sb1[2];

    int tid = threadIdx.x;
    for (int i = tid; i < 288; i += 384) {
        int g = i / 18, t = i % 18;
        spw[i] = pk(wk[(2*g)*18 + t], wk[(2*g+1)*18 + t]);
    }
    if (tid < 16) spb[tid] = pk(bk[2*tid], bk[2*tid+1]);
    if (tid < 32) sr1[tid] = pk(w1[tid], w1[32+tid]);
    if (tid >= 32 && tid < 55)  sw23[tid-32] = g_w23[tid-32];
    if (tid >= 64 && tid < 80)  sw16[tid-64] = g_w16[tid-64];
    if (tid < WW) stw[tid] = g_tw368[tid];
    if (tid >= 80 && tid < 82) sb1[tid-80] = b1[tid-80];
    __syncthreads();

    int b  = blockIdx.x / (HH/RA);
    int h0 = (blockIdx.x % (HH/RA)) * RA;
    const float norm = rsqrtf((float)TOT);

    // ---- conv phase ----
    for (int idx = tid; idx < RA*WW; idx += 384) {
        int r = idx / WW, w = idx % WW;
        int h = h0 + r;
        float x[18];
#pragma unroll
        for (int c = 0; c < 2; c++) {
            const float* base = ks + (size_t)(b*2 + c) * HW;
#pragma unroll
            for (int ky = 0; ky < 3; ky++) {
                int hh = h + ky - 1;
#pragma unroll
                for (int kx = 0; kx < 3; kx++) {
                    int ww = w + kx - 1;
                    float v = 0.0f;
                    if (hh >= 0 && hh < HH && ww >= 0 && ww < WW)
                        v = __ldg(base + hh*WW + ww);
                    x[c*9 + ky*3 + kx] = v;
                }
            }
        }
        u64 xp[18];
#pragma unroll
        for (int t = 0; t < 18; t++) xp[t] = pk(x[t], x[t]);

        u64 o01 = pk(0.0f, 0.0f);
#pragma unroll 4
        for (int g = 0; g < 16; g++) {
            u64 acc = spb[g];
#pragma unroll
            for (int t = 0; t < 18; t++)
                acc = ffma2(xp[t], spw[g*18 + t], acc);
            float a0, a1; upk(acc, a0, a1);
            a0 = leaky(a0); a1 = leaky(a1);
            o01 = ffma2(pk(a0, a0), sr1[2*g],   o01);
            o01 = ffma2(pk(a1, a1), sr1[2*g+1], o01);
        }
        float o0, o1; upk(o01, o0, o1);
        o0 = leaky(o0 + sb1[0]);
        o1 = leaky(o1 + sb1[1]);
        float sgn = ((b + h + w) & 1) ? -norm : norm;
        srow[r][w] = make_float2(o0*sgn, o1*sgn);
    }
    __syncthreads();

    // ---- W FFT stage 1: T[n1*23+k2] = tw368[n1*k2]*sum_n2 x[n1+16*n2]*w23[(n2*k2)%23]
    float2 acc1[RA];
    int n1 = 0, k2 = 0;
    if (tid < WW) {
        n1 = tid / 23; k2 = tid - n1*23;
#pragma unroll
        for (int r = 0; r < RA; r++) {
            float2 a = make_float2(0.0f, 0.0f);
            int idx = 0;
#pragma unroll
            for (int n2 = 0; n2 < 23; n2++) {
                cfma(a, srow[r][n1 + 16*n2], sw23[idx]);
                idx += k2; if (idx >= 23) idx -= 23;
            }
            acc1[r] = cmulf(a, stw[n1*k2]);
        }
    }
    __syncthreads();
    if (tid < WW) {
#pragma unroll
        for (int r = 0; r < RA; r++) srow[r][tid] = acc1[r];   // T layout: index n1*23+k2 == tid
    }
    __syncthreads();

    // ---- W FFT stage 2: X[23*k1+k2] = sum_n1 T[n1*23+k2]*w16[(n1*k1)&15]
    if (tid < WW) {
        int k1 = n1;   // same decomposition of tid
#pragma unroll
        for (int r = 0; r < RA; r++) {
            float2 a = make_float2(0.0f, 0.0f);
#pragma unroll
            for (int m = 0; m < 16; m++)
                cfma(a, srow[r][m*23 + k2], sw16[(m*k1) & 15]);
            g_bufB[(size_t)(b*HH + h0 + r)*WW + tid] = a;
        }
    }
}

// =====================================================================
// Kernel B: H-axis FFT (640 = 32 x 20), both stages fused in smem.
// Reads g_bufB, writes g_bufA. One block per (b, 8-wide w tile).
// =====================================================================
#define WT 8
#define SP 9   // padded row stride (float2 units)
__global__ __launch_bounds__(256) void k_fftH() {
    __shared__ float2     s[HH*SP];   // 46080 B
    __shared__ ulonglong2 sw20[20];
    __shared__ ulonglong2 sw32[32];
    __shared__ float2     stw[HH];    // 5120 B

    int tid = threadIdx.x;
    if (tid < 20) sw20[tid] = g_w20q[tid];
    if (tid >= 32 && tid < 64) sw32[tid-32] = g_w32q[tid-32];
    for (int i = tid; i < HH; i += 256) stw[i] = g_tw640[i];

    int b = blockIdx.x / (WW/WT);
    int wbase = (blockIdx.x % (WW/WT)) * WT;
    const float2* gin = g_bufB + (size_t)b*HW + wbase;

    for (int i = tid; i < HH*WT; i += 256) {
        int h = i >> 3, w = i & 7;
        s[h*SP + w] = gin[(size_t)h*WW + w];
    }
    __syncthreads();

    int lane = tid >> 3;    // 0..31
    int w    = tid & 7;

    // ---- stage 1: lane = n1. T[n1*20+k2] = tw640[n1*k2]*sum_n2 x[n1+32*n2]*w20[(n2*k2)%20]
    u64 acc[20];
#pragma unroll
    for (int k = 0; k < 20; k++) acc[k] = pk(0.0f, 0.0f);
#pragma unroll 4
    for (int n2 = 0; n2 < 20; n2++) {
        float2 v = s[(lane + 32*n2)*SP + w];
        u64 vx = pk(v.x, v.x), vy = pk(-v.y, v.y);
        int idx = 0;
#pragma unroll
        for (int k = 0; k < 20; k++) {
            ulonglong2 q = sw20[idx];
            acc[k] = ffma2(vx, q.x, acc[k]);
            acc[k] = ffma2(vy, q.y, acc[k]);
            idx += n2; if (idx >= 20) idx -= 20;
        }
    }
#pragma unroll
    for (int k = 0; k < 20; k++) {
        float ar, ai; upk(acc[k], ar, ai);
        float2 t = cmulf(make_float2(ar, ai), stw[lane*k]);
        acc[k] = pk(t.x, t.y);
    }
    __syncthreads();
#pragma unroll
    for (int k = 0; k < 20; k++) {
        float ar, ai; upk(acc[k], ar, ai);
        s[(lane*20 + k)*SP + w] = make_float2(ar, ai);
    }
    __syncthreads();

    // ---- stage 2: lane = k1. X[20*k1+k2] = sum_n1 T[n1*20+k2]*w32[(n1*k1)&31]
#pragma unroll
    for (int k = 0; k < 20; k++) acc[k] = pk(0.0f, 0.0f);
#pragma unroll 4
    for (int m = 0; m < 32; m++) {
        ulonglong2 q = sw32[(m*lane) & 31];   // (c,c), (-s,s)
        const float2* row = &s[(m*20)*SP + w];
#pragma unroll
        for (int k = 0; k < 20; k++) {
            float2 v = row[k*SP];
            acc[k] = ffma2(pk(v.x, v.y), q.x, acc[k]);
            acc[k] = ffma2(pk(v.y, v.x), q.y, acc[k]);
        }
    }
    float2* gout = g_bufA + (size_t)b*HW + wbase + w;
#pragma unroll
    for (int k = 0; k < 20; k++) {
        float ar, ai; upk(acc[k], ar, ai);
        gout[(size_t)(20*lane + k)*WW] = make_float2(ar, ai);
    }
}

// =====================================================================
// Kernel C: batch radix-8 DFT + abs + fp16-faithful conv1x1(2->1)+leaky
// Reads g_bufA, writes f32 tmp into g_bufB.
// =====================================================================
__global__ __launch_bounds__(256) void k_babs(const float* __restrict__ img,
        const float* __restrict__ w2, const float* __restrict__ b2) {
    __shared__ ulonglong2 sw8[8];
    if (threadIdx.x < 8) sw8[threadIdx.x] = g_w8q[threadIdx.x];
    __syncthreads();

    int p = blockIdx.x * blockDim.x + threadIdx.x;
    if (p >= HW) return;

    u64 acc[8];
#pragma unroll
    for (int k = 0; k < 8; k++) acc[k] = pk(0.0f, 0.0f);
#pragma unroll
    for (int bb = 0; bb < 8; bb++) {
        float2 v = g_bufA[(size_t)bb*HW + p];
        u64 vx = pk(v.x, v.x), vy = pk(-v.y, v.y);
#pragma unroll
        for (int k = 0; k < 8; k++) {
            ulonglong2 q = sw8[(bb*k) & 7];
            acc[k] = ffma2(vx, q.x, acc[k]);
            acc[k] = ffma2(vy, q.y, acc[k]);
        }
    }

    float cw0 = __half2float(__float2half(__ldg(w2)));
    float cw1 = __half2float(__float2half(__ldg(w2 + 1)));
    __half b2h = __float2half(__ldg(b2));
    const __half slope = __float2half(0.01f);

    float* tmp = (float*)g_bufB;
#pragma unroll
    for (int k = 0; k < 8; k++) {
        float ar, ai; upk(acc[k], ar, ai);
        float im = sqrtf(fmaf(ar, ar, ai*ai));
        float imh  = __half2float(__float2half(im));
        float imgv = __half2float(__float2half(__ldg(img + (size_t)k*HW + p)));
        float y = fmaf(cw1, imgv, cw0*imh);
        __half yh = __float2half(y);
        yh = __hadd(yh, b2h);
        float yf = __half2float(yh);
        float z = (yf >= 0.0f) ? yf : __half2float(__hmul(yh, slope));
        tmp[(size_t)k*HW + p] = z;
    }
}

// ---------------- final conv3x3(1->1) pad1 + leaky -> d_out ----------------
__global__ void k_final(float* __restrict__ out, const float* __restrict__ wi,
                        const float* __restrict__ bi) {
    int pix = blockIdx.x * blockDim.x + threadIdx.x;
    if (pix >= TOT) return;
    int w = pix % WW;
    int h = (pix / WW) % HH;
    int b = pix / HW;
    const float* tmp = (const float*)g_bufB + (size_t)b * HW;
    float acc = __ldg(bi);
#pragma unroll
    for (int ky = 0; ky < 3; ky++) {
        int hh = h + ky - 1;
        if (hh < 0 || hh >= HH) continue;
#pragma unroll
        for (int kx = 0; kx < 3; kx++) {
            int ww = w + kx - 1;
            if (ww < 0 || ww >= WW) continue;
            acc = fmaf(__ldg(wi + ky*3 + kx), tmp[hh*WW + ww], acc);
        }
    }
    out[pix] = acc >= 0.0f ? acc : 0.01f * acc;
}

// ---------------------------------------------------------------------------
extern "C" void kernel_launch(void* const* d_in, const int* in_sizes, int n_in,
                              void* d_out, int out_size) {
    const float* img = (const float*)d_in[0];
    const float* ks  = (const float*)d_in[1];
    const float* wk  = (const float*)d_in[2];
    const float* bk  = (const float*)d_in[3];
    const float* w1  = (const float*)d_in[4];
    const float* b1  = (const float*)d_in[5];
    const float* w2  = (const float*)d_in[6];
    const float* b2  = (const float*)d_in[7];
    const float* wi  = (const float*)d_in[8];
    const float* bi  = (const float*)d_in[9];

    k_init <<<5, 256>>>();
    k_convW<<<BB*(HH/RA), 384>>>(ks, wk, bk, w1, b1);
    k_fftH <<<BB*(WW/WT), 256>>>();
    k_babs <<<(HW + 255)/256, 256>>>(img, w2, b2);
    k_final<<<(TOT + 255)/256, 256>>>((float*)d_out, wi, bi);
}

// round 5
// speedup vs baseline: 1.0823x; 1.0036x over previous
#include <cuda_runtime.h>
#include <cuda_fp16.h>
#include <math.h>

#define BB  8
#define HH  640
#define WW  368
#define HW  (HH*WW)      // 235520
#define TOT (BB*HH*WW)   // 1884160

typedef unsigned long long u64;

// ---------------- scratch ----------------
__device__ float2 g_bufA[TOT];   // 15 MB
__device__ float2 g_bufB[TOT];   // 15 MB

// twiddle tables (e^{+2*pi*i*t/N} -> inverse transform)
__device__ float2 g_w23[23];
__device__ float2 g_w16[16];
__device__ float2 g_tw368[368];
__device__ float2 g_tw640[640];
// packed tables: .x = pk(c,s), .y = pk(s,c)   (value-reuse complex fma form)
__device__ ulonglong2 g_w20q[20];
__device__ ulonglong2 g_w8q[8];
// packed table: .x = pk(c,c), .y = pk(-s,s)   (weight-reuse complex fma form)
__device__ ulonglong2 g_w32q[32];

// ---------------- f32x2 helpers ----------------
__device__ __forceinline__ u64 pk(float lo, float hi) {
    u64 r; asm("mov.b64 %0, {%1, %2};" : "=l"(r) : "f"(lo), "f"(hi)); return r;
}
__device__ __forceinline__ void upk(u64 v, float& lo, float& hi) {
    asm("mov.b64 {%0, %1}, %2;" : "=f"(lo), "=f"(hi) : "l"(v));
}
__device__ __forceinline__ u64 ffma2(u64 a, u64 b, u64 c) {
    u64 d; asm("fma.rn.f32x2 %0, %1, %2, %3;" : "=l"(d) : "l"(a), "l"(b), "l"(c)); return d;
}

__device__ __forceinline__ float2 cmulf(float2 a, float2 b) {
    return make_float2(fmaf(a.x, b.x, -a.y * b.y), fmaf(a.x, b.y, a.y * b.x));
}
__device__ __forceinline__ void cfma(float2& acc, float2 a, float2 b) {
    acc.x = fmaf(a.x, b.x, fmaf(-a.y, b.y, acc.x));
    acc.y = fmaf(a.x, b.y, fmaf( a.y, b.x, acc.y));
}
__device__ __forceinline__ float leaky(float a) {
    return fmaf(0.01f, fminf(a, 0.0f), fmaxf(a, 0.0f));
}

// ---------------- table init ----------------
__device__ __forceinline__ void csN(int N, int i, float& c, float& s) {
    double a = 6.283185307179586476925286766559 * (double)i / (double)N;
    double ds, dc; sincos(a, &ds, &dc);
    c = (float)dc; s = (float)ds;
}
__device__ __forceinline__ u64 pkh(float lo, float hi) {
    return ((u64)__float_as_uint(hi) << 32) | (u64)__float_as_uint(lo);
}

__global__ void k_init() {
    int t = blockIdx.x * blockDim.x + threadIdx.x;
    float c, s;
    if (t < 23)               { csN(23,  t,        c, s); g_w23[t]        = make_float2(c, s); }
    else if (t < 39)          { csN(16,  t-23,     c, s); g_w16[t-23]     = make_float2(c, s); }
    else if (t < 39+368)      { csN(368, t-39,     c, s); g_tw368[t-39]   = make_float2(c, s); }
    else if (t < 407+640)     { csN(640, t-407,    c, s); g_tw640[t-407]  = make_float2(c, s); }
    else if (t < 1047+20)     { csN(20,  t-1047,   c, s); g_w20q[t-1047]  = make_ulonglong2(pkh(c, s), pkh(s, c)); }
    else if (t < 1067+32)     { csN(32,  t-1067,   c, s); g_w32q[t-1067]  = make_ulonglong2(pkh(c, c), pkh(-s, s)); }
    else if (t < 1099+8)      { csN(8,   t-1099,   c, s); g_w8q[t-1099]   = make_ulonglong2(pkh(c, s), pkh(s, c)); }
}

// =====================================================================
// Kernel A: conv3x3(2->32)+leaky + conv1x1(32->2)+leaky  +  W-axis FFT
//           (368 = 16 x 23), fully fused per block of RA rows.
// Writes result (with centered-ifft sign + ortho norm) to g_bufB.
// =====================================================================
#define RA 8
__global__ __launch_bounds__(384) void k_convW(const float* __restrict__ ks,
        const float* __restrict__ wk, const float* __restrict__ bk,
        const float* __restrict__ w1, const float* __restrict__ b1) {
    __shared__ float2 srow[RA][WW];   // 23552 B
    __shared__ u64    spw[288];       // packed conv3x3 weights (16 ch-pairs x 18 taps)
    __shared__ u64    spb[16];
    __shared__ u64    sr1[32];        // (w1[0][o], w1[1][o])
    __shared__ float2 sw23[23];
    __shared__ float2 sw16[16];
    __shared__ float2 stw[WW];
    __shared__ float  sb1[2];

    int tid = threadIdx.x;
    for (int i = tid; i < 288; i += 384) {
        int g = i / 18, t = i % 18;
        spw[i] = pk(wk[(2*g)*18 + t], wk[(2*g+1)*18 + t]);
    }
    if (tid < 16) spb[tid] = pk(bk[2*tid], bk[2*tid+1]);
    if (tid < 32) sr1[tid] = pk(w1[tid], w1[32+tid]);
    if (tid >= 32 && tid < 55)  sw23[tid-32] = g_w23[tid-32];
    if (tid >= 64 && tid < 80)  sw16[tid-64] = g_w16[tid-64];
    if (tid < WW) stw[tid] = g_tw368[tid];
    if (tid >= 80 && tid < 82) sb1[tid-80] = b1[tid-80];
    __syncthreads();

    int b  = blockIdx.x / (HH/RA);
    int h0 = (blockIdx.x % (HH/RA)) * RA;
    const float norm = rsqrtf((float)TOT);

    // ---- conv phase ----
    for (int idx = tid; idx < RA*WW; idx += 384) {
        int r = idx / WW, w = idx % WW;
        int h = h0 + r;
        float x[18];
#pragma unroll
        for (int c = 0; c < 2; c++) {
            const float* base = ks + (size_t)(b*2 + c) * HW;
#pragma unroll
            for (int ky = 0; ky < 3; ky++) {
                int hh = h + ky - 1;
#pragma unroll
                for (int kx = 0; kx < 3; kx++) {
                    int ww = w + kx - 1;
                    float v = 0.0f;
                    if (hh >= 0 && hh < HH && ww >= 0 && ww < WW)
                        v = __ldg(base + hh*WW + ww);
                    x[c*9 + ky*3 + kx] = v;
                }
            }
        }
        u64 xp[18];
#pragma unroll
        for (int t = 0; t < 18; t++) xp[t] = pk(x[t], x[t]);

        u64 o01 = pk(0.0f, 0.0f);
#pragma unroll 4
        for (int g = 0; g < 16; g++) {
            u64 acc = spb[g];
#pragma unroll
            for (int t = 0; t < 18; t++)
                acc = ffma2(xp[t], spw[g*18 + t], acc);
            float a0, a1; upk(acc, a0, a1);
            a0 = leaky(a0); a1 = leaky(a1);
            o01 = ffma2(pk(a0, a0), sr1[2*g],   o01);
            o01 = ffma2(pk(a1, a1), sr1[2*g+1], o01);
        }
        float o0, o1; upk(o01, o0, o1);
        o0 = leaky(o0 + sb1[0]);
        o1 = leaky(o1 + sb1[1]);
        float sgn = ((b + h + w) & 1) ? -norm : norm;
        srow[r][w] = make_float2(o0*sgn, o1*sgn);
    }
    __syncthreads();

    // ---- W FFT stage 1: T[n1*23+k2] = tw368[n1*k2]*sum_n2 x[n1+16*n2]*w23[(n2*k2)%23]
    float2 acc1[RA];
    int n1 = 0, k2 = 0;
    if (tid < WW) {
        n1 = tid / 23; k2 = tid - n1*23;
#pragma unroll
        for (int r = 0; r < RA; r++) {
            float2 a = make_float2(0.0f, 0.0f);
            int idx = 0;
#pragma unroll
            for (int n2 = 0; n2 < 23; n2++) {
                cfma(a, srow[r][n1 + 16*n2], sw23[idx]);
                idx += k2; if (idx >= 23) idx -= 23;
            }
            acc1[r] = cmulf(a, stw[n1*k2]);
        }
    }
    __syncthreads();
    if (tid < WW) {
#pragma unroll
        for (int r = 0; r < RA; r++) srow[r][tid] = acc1[r];   // T layout: index n1*23+k2 == tid
    }
    __syncthreads();

    // ---- W FFT stage 2: X[23*k1+k2] = sum_n1 T[n1*23+k2]*w16[(n1*k1)&15]
    if (tid < WW) {
        int k1 = n1;   // same decomposition of tid
#pragma unroll
        for (int r = 0; r < RA; r++) {
            float2 a = make_float2(0.0f, 0.0f);
#pragma unroll
            for (int m = 0; m < 16; m++)
                cfma(a, srow[r][m*23 + k2], sw16[(m*k1) & 15]);
            g_bufB[(size_t)(b*HH + h0 + r)*WW + tid] = a;
        }
    }
}

// =====================================================================
// Kernel B: H-axis FFT (640 = 32 x 20), both stages fused in smem.
// Reads g_bufB, writes g_bufA. One block per (b, 8-wide w tile).
// =====================================================================
#define WT 8
#define SP 9   // padded row stride (float2 units)
__global__ __launch_bounds__(256) void k_fftH() {
    __shared__ float2     s[HH*SP];   // 46080 B
    __shared__ ulonglong2 sw20[20];
    __shared__ ulonglong2 sw32[32];
    __shared__ float2     stw[HH];    // 5120 B

    int tid = threadIdx.x;
    if (tid < 20) sw20[tid] = g_w20q[tid];
    if (tid >= 32 && tid < 64) sw32[tid-32] = g_w32q[tid-32];
    for (int i = tid; i < HH; i += 256) stw[i] = g_tw640[i];

    int b = blockIdx.x / (WW/WT);
    int wbase = (blockIdx.x % (WW/WT)) * WT;
    const float2* gin = g_bufB + (size_t)b*HW + wbase;

    for (int i = tid; i < HH*WT; i += 256) {
        int h = i >> 3, w = i & 7;
        s[h*SP + w] = gin[(size_t)h*WW + w];
    }
    __syncthreads();

    int lane = tid >> 3;    // 0..31
    int w    = tid & 7;

    // ---- stage 1: lane = n1. T[n1*20+k2] = tw640[n1*k2]*sum_n2 x[n1+32*n2]*w20[(n2*k2)%20]
    u64 acc[20];
#pragma unroll
    for (int k = 0; k < 20; k++) acc[k] = pk(0.0f, 0.0f);
#pragma unroll 4
    for (int n2 = 0; n2 < 20; n2++) {
        float2 v = s[(lane + 32*n2)*SP + w];
        u64 vx = pk(v.x, v.x), vy = pk(-v.y, v.y);
        int idx = 0;
#pragma unroll
        for (int k = 0; k < 20; k++) {
            ulonglong2 q = sw20[idx];
            acc[k] = ffma2(vx, q.x, acc[k]);
            acc[k] = ffma2(vy, q.y, acc[k]);
            idx += n2; if (idx >= 20) idx -= 20;
        }
    }
#pragma unroll
    for (int k = 0; k < 20; k++) {
        float ar, ai; upk(acc[k], ar, ai);
        float2 t = cmulf(make_float2(ar, ai), stw[lane*k]);
        acc[k] = pk(t.x, t.y);
    }
    __syncthreads();
#pragma unroll
    for (int k = 0; k < 20; k++) {
        float ar, ai; upk(acc[k], ar, ai);
        s[(lane*20 + k)*SP + w] = make_float2(ar, ai);
    }
    __syncthreads();

    // ---- stage 2: lane = k1. X[20*k1+k2] = sum_n1 T[n1*20+k2]*w32[(n1*k1)&31]
#pragma unroll
    for (int k = 0; k < 20; k++) acc[k] = pk(0.0f, 0.0f);
#pragma unroll 4
    for (int m = 0; m < 32; m++) {
        ulonglong2 q = sw32[(m*lane) & 31];   // (c,c), (-s,s)
        const float2* row = &s[(m*20)*SP + w];
#pragma unroll
        for (int k = 0; k < 20; k++) {
            float2 v = row[k*SP];
            acc[k] = ffma2(pk(v.x, v.y), q.x, acc[k]);
            acc[k] = ffma2(pk(v.y, v.x), q.y, acc[k]);
        }
    }
    float2* gout = g_bufA + (size_t)b*HW + wbase + w;
#pragma unroll
    for (int k = 0; k < 20; k++) {
        float ar, ai; upk(acc[k], ar, ai);
        gout[(size_t)(20*lane + k)*WW] = make_float2(ar, ai);
    }
}

// =====================================================================
// Kernel C: batch radix-8 DFT + abs + fp16-faithful conv1x1(2->1)+leaky
// Reads g_bufA, writes f32 tmp into g_bufB.
// =====================================================================
__global__ __launch_bounds__(256) void k_babs(const float* __restrict__ img,
        const float* __restrict__ w2, const float* __restrict__ b2) {
    __shared__ ulonglong2 sw8[8];
    if (threadIdx.x < 8) sw8[threadIdx.x] = g_w8q[threadIdx.x];
    __syncthreads();

    int p = blockIdx.x * blockDim.x + threadIdx.x;
    if (p >= HW) return;

    u64 acc[8];
#pragma unroll
    for (int k = 0; k < 8; k++) acc[k] = pk(0.0f, 0.0f);
#pragma unroll
    for (int bb = 0; bb < 8; bb++) {
        float2 v = g_bufA[(size_t)bb*HW + p];
        u64 vx = pk(v.x, v.x), vy = pk(-v.y, v.y);
#pragma unroll
        for (int k = 0; k < 8; k++) {
            ulonglong2 q = sw8[(bb*k) & 7];
            acc[k] = ffma2(vx, q.x, acc[k]);
            acc[k] = ffma2(vy, q.y, acc[k]);
        }
    }

    float cw0 = __half2float(__float2half(__ldg(w2)));
    float cw1 = __half2float(__float2half(__ldg(w2 + 1)));
    __half b2h = __float2half(__ldg(b2));
    const __half slope = __float2half(0.01f);

    float* tmp = (float*)g_bufB;
#pragma unroll
    for (int k = 0; k < 8; k++) {
        float ar, ai; upk(acc[k], ar, ai);
        float im = sqrtf(fmaf(ar, ar, ai*ai));
        float imh  = __half2float(__float2half(im));
        float imgv = __half2float(__float2half(__ldg(img + (size_t)k*HW + p)));
        float y = fmaf(cw1, imgv, cw0*imh);
        __half yh = __float2half(y);
        yh = __hadd(yh, b2h);
        float yf = __half2float(yh);
        float z = (yf >= 0.0f) ? yf : __half2float(__hmul(yh, slope));
        tmp[(size_t)k*HW + p] = z;
    }
}

// ---------------- final conv3x3(1->1) pad1 + leaky -> d_out ----------------
__global__ void k_final(float* __restrict__ out, const float* __restrict__ wi,
                        const float* __restrict__ bi) {
    int pix = blockIdx.x * blockDim.x + threadIdx.x;
    if (pix >= TOT) return;
    int w = pix % WW;
    int h = (pix / WW) % HH;
    int b = pix / HW;
    const float* tmp = (const float*)g_bufB + (size_t)b * HW;
    float acc = __ldg(bi);
#pragma unroll
    for (int ky = 0; ky < 3; ky++) {
        int hh = h + ky - 1;
        if (hh < 0 || hh >= HH) continue;
#pragma unroll
        for (int kx = 0; kx < 3; kx++) {
            int ww = w + kx - 1;
            if (ww < 0 || ww >= WW) continue;
            acc = fmaf(__ldg(wi + ky*3 + kx), tmp[hh*WW + ww], acc);
        }
    }
    out[pix] = acc >= 0.0f ? acc : 0.01f * acc;
}

// ---------------------------------------------------------------------------
extern "C" void kernel_launch(void* const* d_in, const int* in_sizes, int n_in,
                              void* d_out, int out_size) {
    const float* img = (const float*)d_in[0];
    const float* ks  = (const float*)d_in[1];
    const float* wk  = (const float*)d_in[2];
    const float* bk  = (const float*)d_in[3];
    const float* w1  = (const float*)d_in[4];
    const float* b1  = (const float*)d_in[5];
    const float* w2  = (const float*)d_in[6];
    const float* b2  = (const float*)d_in[7];
    const float* wi  = (const float*)d_in[8];
    const float* bi  = (const float*)d_in[9];

    k_init <<<5, 256>>>();
    k_convW<<<BB*(HH/RA), 384>>>(ks, wk, bk, w1, b1);
    k_fftH <<<BB*(WW/WT), 256>>>();
    k_babs <<<(HW + 255)/256, 256>>>(img, w2, b2);
    k_final<<<(TOT + 255)/256, 256>>>((float*)d_out, wi, bi);
}